// round 1
// baseline (speedup 1.0000x reference)
#include <cuda_runtime.h>

#define D_MODEL 1024
#define NHEAD   16
#define HD      64
#define SEQ     2048
#define BATCH   2
#define M_TOT   (BATCH * SEQ)   // 4096
#define QKV_W   (3 * D_MODEL)   // 3072

// Scratch (no cudaMalloc allowed): qkv projection output and attention output.
__device__ float g_qkv[(size_t)M_TOT * QKV_W];   // [4096, 3072]
__device__ float g_ao [(size_t)M_TOT * D_MODEL]; // [4096, 1024]

// ---------------------------------------------------------------------------
// C[m][n] = sum_k A[m][k] * B[n][k]   (both operands K-major, row-major)
// 64x64 block tile, 16 K-tile, 256 threads, 4x4 per-thread micro-tile.
// ---------------------------------------------------------------------------
__global__ void gemm_kmajor(const float* __restrict__ A,
                            const float* __restrict__ B,
                            float* __restrict__ C,
                            int M, int N, int K) {
    __shared__ float As[16][65];   // +1 pad: conflict-free transposed stores
    __shared__ float Bs[16][65];

    const int t  = threadIdx.x;
    const int tx = t & 15;          // 0..15  (N direction)
    const int ty = t >> 4;          // 0..15  (M direction)
    const int m0 = blockIdx.y * 64;
    const int n0 = blockIdx.x * 64;

    const int lrow = t >> 2;        // 0..63 row to load
    const int lk   = (t & 3) << 2;  // 0,4,8,12 k offset (float4)

    float acc[4][4];
#pragma unroll
    for (int i = 0; i < 4; i++)
#pragma unroll
        for (int j = 0; j < 4; j++) acc[i][j] = 0.f;

    for (int k0 = 0; k0 < K; k0 += 16) {
        float4 a  = *(const float4*)(A + (size_t)(m0 + lrow) * K + k0 + lk);
        float4 bv = *(const float4*)(B + (size_t)(n0 + lrow) * K + k0 + lk);
        As[lk + 0][lrow] = a.x;  As[lk + 1][lrow] = a.y;
        As[lk + 2][lrow] = a.z;  As[lk + 3][lrow] = a.w;
        Bs[lk + 0][lrow] = bv.x; Bs[lk + 1][lrow] = bv.y;
        Bs[lk + 2][lrow] = bv.z; Bs[lk + 3][lrow] = bv.w;
        __syncthreads();

#pragma unroll
        for (int kk = 0; kk < 16; kk++) {
            float av[4], bw[4];
#pragma unroll
            for (int i = 0; i < 4; i++) {
                av[i] = As[kk][ty * 4 + i];
                bw[i] = Bs[kk][tx * 4 + i];
            }
#pragma unroll
            for (int i = 0; i < 4; i++)
#pragma unroll
                for (int j = 0; j < 4; j++)
                    acc[i][j] = fmaf(av[i], bw[j], acc[i][j]);
        }
        __syncthreads();
    }

#pragma unroll
    for (int i = 0; i < 4; i++) {
        const size_t m = (size_t)(m0 + ty * 4 + i);
#pragma unroll
        for (int j = 0; j < 4; j++)
            C[m * N + n0 + tx * 4 + j] = acc[i][j];
    }
}

// ---------------------------------------------------------------------------
// Causal flash attention.
// Grid: (32 q-tiles, 16 heads, 2 batch). Block: 256 threads.
// Each block: 64 queries x full head_dim 64. Iterates 64-key tiles.
// Thread layout: r = tid/4 (query row), cg = tid%4 (group of 16 cols).
// Q row kept fully in registers (16 float4). K,V,P tiles in smem (48KB).
// ---------------------------------------------------------------------------
__global__ void attn_kernel(const float* __restrict__ qkv,
                            float* __restrict__ out) {
    __shared__ float Ks[64][64];
    __shared__ float Vs[64][64];
    __shared__ float Ps[64][64];

    const int qt = blockIdx.x;
    const int h  = blockIdx.y;
    const int b  = blockIdx.z;
    const int t  = threadIdx.x;
    const int r  = t >> 2;        // query row within tile
    const int cg = t & 3;         // column group (16 wide)
    const int q0 = qt * 64;
    const float scale = 0.125f;   // 1/sqrt(64)

    // Q row -> registers
    float4 qreg[16];
    {
        const float* qp = qkv + (size_t)(b * SEQ + q0 + r) * QKV_W + h * HD;
#pragma unroll
        for (int i = 0; i < 16; i++) qreg[i] = ((const float4*)qp)[i];
    }

    float m_i = -1e30f, l_i = 0.f;
    float acc[16];
#pragma unroll
    for (int i = 0; i < 16; i++) acc[i] = 0.f;

    for (int j = 0; j <= qt; j++) {
        const int k0 = j * 64;
        // load K,V tile: 64 rows x 16 float4 each
        {
            const float* kp = qkv + (size_t)(b * SEQ + k0) * QKV_W + D_MODEL     + h * HD;
            const float* vp = qkv + (size_t)(b * SEQ + k0) * QKV_W + 2 * D_MODEL + h * HD;
#pragma unroll
            for (int e = t; e < 1024; e += 256) {
                const int row = e >> 4, f4 = e & 15;
                ((float4*)&Ks[row][0])[f4] = *(const float4*)(kp + (size_t)row * QKV_W + f4 * 4);
                ((float4*)&Vs[row][0])[f4] = *(const float4*)(vp + (size_t)row * QKV_W + f4 * 4);
            }
        }
        __syncthreads();

        // scores for my 16 key columns
        float s[16];
#pragma unroll
        for (int cc = 0; cc < 16; cc++) {
            const int c = cg * 16 + cc;
            const float4* krow = (const float4*)&Ks[c][0];
            float dot = 0.f;
#pragma unroll
            for (int i = 0; i < 16; i++) {
                float4 kv = krow[i];
                dot = fmaf(qreg[i].x, kv.x, dot);
                dot = fmaf(qreg[i].y, kv.y, dot);
                dot = fmaf(qreg[i].z, kv.z, dot);
                dot = fmaf(qreg[i].w, kv.w, dot);
            }
            s[cc] = dot * scale;
            if (j == qt && (k0 + c) > (q0 + r)) s[cc] = -1e30f;
        }

        // row max across 16 local cols then across the 4 threads of this row
        float mx = s[0];
#pragma unroll
        for (int cc = 1; cc < 16; cc++) mx = fmaxf(mx, s[cc]);
        mx = fmaxf(mx, __shfl_xor_sync(0xffffffffu, mx, 1));
        mx = fmaxf(mx, __shfl_xor_sync(0xffffffffu, mx, 2));

        const float m_new = fmaxf(m_i, mx);
        const float alpha = __expf(m_i - m_new);

        float rs = 0.f;
#pragma unroll
        for (int cc = 0; cc < 16; cc++) {
            const float p = __expf(s[cc] - m_new);
            Ps[r][cg * 16 + cc] = p;
            rs += p;
        }
        rs += __shfl_xor_sync(0xffffffffu, rs, 1);
        rs += __shfl_xor_sync(0xffffffffu, rs, 2);

        l_i = l_i * alpha + rs;
        m_i = m_new;
#pragma unroll
        for (int dd = 0; dd < 16; dd++) acc[dd] *= alpha;

        __syncthreads();  // Ps fully written before full-row reads

        // O += P @ V  (my 16 head-dim columns)
#pragma unroll
        for (int c = 0; c < 64; c++) {
            const float p = Ps[r][c];
            const float4* vrow = (const float4*)&Vs[c][cg * 16];
#pragma unroll
            for (int i = 0; i < 4; i++) {
                const float4 vv = vrow[i];
                acc[i * 4 + 0] = fmaf(p, vv.x, acc[i * 4 + 0]);
                acc[i * 4 + 1] = fmaf(p, vv.y, acc[i * 4 + 1]);
                acc[i * 4 + 2] = fmaf(p, vv.z, acc[i * 4 + 2]);
                acc[i * 4 + 3] = fmaf(p, vv.w, acc[i * 4 + 3]);
            }
        }
        __syncthreads();  // before next tile overwrites Ks/Vs/Ps
    }

    const float inv = 1.f / l_i;
    float* op = out + (size_t)(b * SEQ + q0 + r) * D_MODEL + h * HD + cg * 16;
#pragma unroll
    for (int i = 0; i < 4; i++) {
        float4 o;
        o.x = acc[i * 4 + 0] * inv;
        o.y = acc[i * 4 + 1] * inv;
        o.z = acc[i * 4 + 2] * inv;
        o.w = acc[i * 4 + 3] * inv;
        ((float4*)op)[i] = o;
    }
}

extern "C" void kernel_launch(void* const* d_in, const int* in_sizes, int n_in,
                              void* d_out, int out_size) {
    const float* x     = (const float*)d_in[0];
    const float* w_qkv = (const float*)d_in[1];
    const float* w_o   = (const float*)d_in[2];
    float* out         = (float*)d_out;

    float *qkv, *ao;
    cudaGetSymbolAddress((void**)&qkv, g_qkv);
    cudaGetSymbolAddress((void**)&ao,  g_ao);

    dim3 blk(256);

    // 1) QKV projection: [4096,1024] x [3072,1024]^T -> [4096,3072]
    gemm_kmajor<<<dim3(QKV_W / 64, M_TOT / 64), blk>>>(x, w_qkv, qkv, M_TOT, QKV_W, D_MODEL);

    // 2) causal attention -> [4096,1024]
    attn_kernel<<<dim3(SEQ / 64, NHEAD, BATCH), blk>>>(qkv, ao);

    // 3) output projection: [4096,1024] x [1024,1024]^T -> d_out
    gemm_kmajor<<<dim3(D_MODEL / 64, M_TOT / 64), blk>>>(ao, w_o, out, M_TOT, D_MODEL, D_MODEL);
}

// round 2
// speedup vs baseline: 8.8163x; 8.8163x over previous
#include <cuda_runtime.h>

#define D_MODEL 1024
#define NHEAD   16
#define HD      64
#define SEQ     2048
#define BATCH   2
#define M_TOT   (BATCH * SEQ)   // 4096
#define QKV_W   (3 * D_MODEL)   // 3072

// Scratch (no cudaMalloc allowed).
__device__ float g_qkv[(size_t)M_TOT * QKV_W];   // [4096, 3072]
__device__ float g_ao [(size_t)M_TOT * D_MODEL]; // [4096, 1024]

__device__ __forceinline__ unsigned f2tf(float f) {
    unsigned u;
    asm("cvt.rna.tf32.f32 %0, %1;" : "=r"(u) : "f"(f));
    return u;
}

// D = A(tf32, m16k8 row) x B(tf32, k8n8 col) + D (fp32)
__device__ __forceinline__ void mma_tf32(float* c, const unsigned* a,
                                         unsigned b0, unsigned b1) {
    asm volatile(
        "mma.sync.aligned.m16n8k8.row.col.f32.tf32.tf32.f32 "
        "{%0,%1,%2,%3},{%4,%5,%6,%7},{%8,%9},{%0,%1,%2,%3};\n"
        : "+f"(c[0]), "+f"(c[1]), "+f"(c[2]), "+f"(c[3])
        : "r"(a[0]), "r"(a[1]), "r"(a[2]), "r"(a[3]), "r"(b0), "r"(b1));
}

// ---------------------------------------------------------------------------
// C[m][n] = sum_k A[m][k] * B[n][k]   (A:[M,K], B:[N,K], both row-major)
// 128x128 block tile, K-tile 32, 256 threads (8 warps, 2x4), tf32 mma.
// smem stride 36 floats: bank = (4*row + col) % 32 -> conflict-free frags.
// ---------------------------------------------------------------------------
__global__ __launch_bounds__(256, 1)
void gemm_tf32(const float* __restrict__ A, const float* __restrict__ B,
               float* __restrict__ C, int M, int N, int K) {
    __shared__ unsigned As[128][36];
    __shared__ unsigned Bs[128][36];

    const int t    = threadIdx.x;
    const int lane = t & 31;
    const int w    = t >> 5;
    const int gid  = lane >> 2;   // 0..7
    const int tig  = lane & 3;    // 0..3
    const int wm   = w & 1;       // 0..1 -> 64-row slice
    const int wn   = w >> 1;      // 0..3 -> 32-col slice
    const int m0   = blockIdx.y * 128;
    const int n0   = blockIdx.x * 128;

    const int lr = t >> 3;        // 0..31 (row within pass)
    const int lc = (t & 7) * 4;   // 0..28 (k col, float4)

    float acc[4][4][4];
#pragma unroll
    for (int i = 0; i < 4; i++)
#pragma unroll
        for (int j = 0; j < 4; j++)
#pragma unroll
            for (int e = 0; e < 4; e++) acc[i][j][e] = 0.f;

    const float* Ap = A + (size_t)(m0 + lr) * K + lc;
    const float* Bp = B + (size_t)(n0 + lr) * K + lc;

    float4 ra[4], rb[4];
#pragma unroll
    for (int p = 0; p < 4; p++) {
        ra[p] = *(const float4*)(Ap + (size_t)(p * 32) * K);
        rb[p] = *(const float4*)(Bp + (size_t)(p * 32) * K);
    }

    const int nkt = K / 32;
    for (int kt = 0; kt < nkt; kt++) {
        // store prefetched tile to smem (convert to tf32 once)
#pragma unroll
        for (int p = 0; p < 4; p++) {
            uint4 ua = make_uint4(f2tf(ra[p].x), f2tf(ra[p].y), f2tf(ra[p].z), f2tf(ra[p].w));
            uint4 ub = make_uint4(f2tf(rb[p].x), f2tf(rb[p].y), f2tf(rb[p].z), f2tf(rb[p].w));
            *(uint4*)&As[p * 32 + lr][lc] = ua;
            *(uint4*)&Bs[p * 32 + lr][lc] = ub;
        }
        __syncthreads();

        if (kt + 1 < nkt) {
            const float* Ap2 = Ap + (kt + 1) * 32;
            const float* Bp2 = Bp + (kt + 1) * 32;
#pragma unroll
            for (int p = 0; p < 4; p++) {
                ra[p] = *(const float4*)(Ap2 + (size_t)(p * 32) * K);
                rb[p] = *(const float4*)(Bp2 + (size_t)(p * 32) * K);
            }
        }

        const int am = wm * 64;
        const int bn = wn * 32;
#pragma unroll
        for (int s = 0; s < 4; s++) {
            const int kk = s * 8;
            unsigned av[4][4];
#pragma unroll
            for (int mi = 0; mi < 4; mi++) {
                const int r = am + 16 * mi + gid;
                av[mi][0] = As[r][kk + tig];
                av[mi][1] = As[r + 8][kk + tig];
                av[mi][2] = As[r][kk + tig + 4];
                av[mi][3] = As[r + 8][kk + tig + 4];
            }
            unsigned bv[4][2];
#pragma unroll
            for (int nj = 0; nj < 4; nj++) {
                const int r = bn + 8 * nj + gid;
                bv[nj][0] = Bs[r][kk + tig];
                bv[nj][1] = Bs[r][kk + tig + 4];
            }
#pragma unroll
            for (int mi = 0; mi < 4; mi++)
#pragma unroll
                for (int nj = 0; nj < 4; nj++)
                    mma_tf32(acc[mi][nj], av[mi], bv[nj][0], bv[nj][1]);
        }
        __syncthreads();
    }

    // epilogue
#pragma unroll
    for (int mi = 0; mi < 4; mi++) {
        const int r = m0 + wm * 64 + 16 * mi + gid;
#pragma unroll
        for (int nj = 0; nj < 4; nj++) {
            const int c = n0 + wn * 32 + 8 * nj + 2 * tig;
            *(float2*)(C + (size_t)r * N + c)       = make_float2(acc[mi][nj][0], acc[mi][nj][1]);
            *(float2*)(C + (size_t)(r + 8) * N + c) = make_float2(acc[mi][nj][2], acc[mi][nj][3]);
        }
    }
}

// ---------------------------------------------------------------------------
// Causal flash attention with tf32 mma.
// Grid (32 q-tiles, 16 heads, 2 batch), 128 threads (4 warps).
// Warp w owns query rows [16w, 16w+16). Q frags in registers (pre-scaled).
// smem: Ks[64][68], Vs[64][72], Ps[64][68]  (strides chosen conflict-free).
// ---------------------------------------------------------------------------
#define KS_STRIDE 68
#define VS_STRIDE 72
#define PS_STRIDE 68
#define SMEM_ATTN ((64 * KS_STRIDE + 64 * VS_STRIDE + 64 * PS_STRIDE) * 4)

__global__ __launch_bounds__(128, 1)
void attn_tf32(const float* __restrict__ qkv, float* __restrict__ out) {
    extern __shared__ unsigned sm[];
    unsigned* Ks = sm;
    unsigned* Vs = Ks + 64 * KS_STRIDE;
    unsigned* Ps = Vs + 64 * VS_STRIDE;

    const int qt   = blockIdx.x;
    const int h    = blockIdx.y;
    const int b    = blockIdx.z;
    const int t    = threadIdx.x;
    const int lane = t & 31;
    const int w    = t >> 5;
    const int gid  = lane >> 2;
    const int tig  = lane & 3;
    const int q0   = qt * 64;

    // cooperative Q load -> Ps (scaled by 1/8, tf32)
    {
        const float* qp = qkv + (size_t)(b * SEQ + q0) * QKV_W + h * HD;
#pragma unroll
        for (int p = 0; p < 8; p++) {
            const int row = p * 8 + (t >> 4);
            const int c4  = (t & 15) * 4;
            float4 v = *(const float4*)(qp + (size_t)row * QKV_W + c4);
            uint4 u = make_uint4(f2tf(v.x * 0.125f), f2tf(v.y * 0.125f),
                                 f2tf(v.z * 0.125f), f2tf(v.w * 0.125f));
            *(uint4*)&Ps[row * PS_STRIDE + c4] = u;
        }
    }
    __syncthreads();

    // Q fragments -> registers
    unsigned qf[8][4];
    {
        const int r0 = (16 * w + gid) * PS_STRIDE;
        const int r1 = (16 * w + gid + 8) * PS_STRIDE;
#pragma unroll
        for (int s = 0; s < 8; s++) {
            qf[s][0] = Ps[r0 + 8 * s + tig];
            qf[s][1] = Ps[r1 + 8 * s + tig];
            qf[s][2] = Ps[r0 + 8 * s + tig + 4];
            qf[s][3] = Ps[r1 + 8 * s + tig + 4];
        }
    }

    float o[8][4];
#pragma unroll
    for (int j = 0; j < 8; j++)
#pragma unroll
        for (int e = 0; e < 4; e++) o[j][e] = 0.f;
    float m0 = -1e30f, m1 = -1e30f, l0 = 0.f, l1 = 0.f;

    const int row0 = q0 + 16 * w + gid;   // global query row (this thread, low)

    for (int jt = 0; jt <= qt; jt++) {
        const int k0 = jt * 64;
        __syncthreads();   // previous tile's Ks/Vs reads done

        // load K,V tile
        {
            const float* kp = qkv + (size_t)(b * SEQ + k0) * QKV_W + D_MODEL + h * HD;
            const float* vp = kp + D_MODEL;
#pragma unroll
            for (int p = 0; p < 8; p++) {
                const int row = p * 8 + (t >> 4);
                const int c4  = (t & 15) * 4;
                float4 kv = *(const float4*)(kp + (size_t)row * QKV_W + c4);
                float4 vv = *(const float4*)(vp + (size_t)row * QKV_W + c4);
                *(uint4*)&Ks[row * KS_STRIDE + c4] =
                    make_uint4(f2tf(kv.x), f2tf(kv.y), f2tf(kv.z), f2tf(kv.w));
                *(uint4*)&Vs[row * VS_STRIDE + c4] =
                    make_uint4(f2tf(vv.x), f2tf(vv.y), f2tf(vv.z), f2tf(vv.w));
            }
        }
        __syncthreads();

        // S = Q K^T  (m16 x n64 per warp)
        float sacc[8][4];
#pragma unroll
        for (int j = 0; j < 8; j++)
#pragma unroll
            for (int e = 0; e < 4; e++) sacc[j][e] = 0.f;

#pragma unroll
        for (int s = 0; s < 8; s++) {
#pragma unroll
            for (int j = 0; j < 8; j++) {
                const int kr = (8 * j + gid) * KS_STRIDE + 8 * s + tig;
                mma_tf32(sacc[j], qf[s], Ks[kr], Ks[kr + 4]);
            }
        }

        // mask (diagonal tile) + row max
        float mt0 = -1e30f, mt1 = -1e30f;
#pragma unroll
        for (int j = 0; j < 8; j++) {
            const int cb = k0 + 8 * j + 2 * tig;
            if (jt == qt) {
                if (cb     > row0)     sacc[j][0] = -1e30f;
                if (cb + 1 > row0)     sacc[j][1] = -1e30f;
                if (cb     > row0 + 8) sacc[j][2] = -1e30f;
                if (cb + 1 > row0 + 8) sacc[j][3] = -1e30f;
            }
            mt0 = fmaxf(mt0, fmaxf(sacc[j][0], sacc[j][1]));
            mt1 = fmaxf(mt1, fmaxf(sacc[j][2], sacc[j][3]));
        }
        mt0 = fmaxf(mt0, __shfl_xor_sync(0xffffffffu, mt0, 1));
        mt0 = fmaxf(mt0, __shfl_xor_sync(0xffffffffu, mt0, 2));
        mt1 = fmaxf(mt1, __shfl_xor_sync(0xffffffffu, mt1, 1));
        mt1 = fmaxf(mt1, __shfl_xor_sync(0xffffffffu, mt1, 2));

        const float mn0 = fmaxf(m0, mt0);
        const float mn1 = fmaxf(m1, mt1);
        const float al0 = __expf(m0 - mn0);
        const float al1 = __expf(m1 - mn1);
        m0 = mn0; m1 = mn1;

        // P = exp(S - m), store tf32 to warp-private Ps rows, row sums
        float ls0 = 0.f, ls1 = 0.f;
        {
            const int pr0 = (16 * w + gid) * PS_STRIDE;
            const int pr1 = (16 * w + gid + 8) * PS_STRIDE;
#pragma unroll
            for (int j = 0; j < 8; j++) {
                const int c = 8 * j + 2 * tig;
                float p00 = __expf(sacc[j][0] - mn0);
                float p01 = __expf(sacc[j][1] - mn0);
                float p10 = __expf(sacc[j][2] - mn1);
                float p11 = __expf(sacc[j][3] - mn1);
                ls0 += p00 + p01;
                ls1 += p10 + p11;
                Ps[pr0 + c]     = f2tf(p00);
                Ps[pr0 + c + 1] = f2tf(p01);
                Ps[pr1 + c]     = f2tf(p10);
                Ps[pr1 + c + 1] = f2tf(p11);
            }
        }
        ls0 += __shfl_xor_sync(0xffffffffu, ls0, 1);
        ls0 += __shfl_xor_sync(0xffffffffu, ls0, 2);
        ls1 += __shfl_xor_sync(0xffffffffu, ls1, 1);
        ls1 += __shfl_xor_sync(0xffffffffu, ls1, 2);
        l0 = l0 * al0 + ls0;
        l1 = l1 * al1 + ls1;

        // rescale O
#pragma unroll
        for (int j = 0; j < 8; j++) {
            o[j][0] *= al0; o[j][1] *= al0;
            o[j][2] *= al1; o[j][3] *= al1;
        }
        __syncwarp();

        // O += P V   (A = P frags from warp-private Ps rows)
#pragma unroll
        for (int s = 0; s < 8; s++) {
            unsigned pa[4];
            const int pr0 = (16 * w + gid) * PS_STRIDE + 8 * s;
            const int pr1 = (16 * w + gid + 8) * PS_STRIDE + 8 * s;
            pa[0] = Ps[pr0 + tig];
            pa[1] = Ps[pr1 + tig];
            pa[2] = Ps[pr0 + tig + 4];
            pa[3] = Ps[pr1 + tig + 4];
#pragma unroll
            for (int j = 0; j < 8; j++) {
                const int vb = (8 * s + tig) * VS_STRIDE + 8 * j + gid;
                mma_tf32(o[j], pa, Vs[vb], Vs[vb + 4 * VS_STRIDE]);
            }
        }
    }

    // epilogue
    const float i0 = 1.f / l0;
    const float i1 = 1.f / l1;
    float* op0 = out + (size_t)(b * SEQ + row0) * D_MODEL + h * HD;
    float* op1 = op0 + (size_t)8 * D_MODEL;
#pragma unroll
    for (int j = 0; j < 8; j++) {
        const int c = 8 * j + 2 * tig;
        *(float2*)(op0 + c) = make_float2(o[j][0] * i0, o[j][1] * i0);
        *(float2*)(op1 + c) = make_float2(o[j][2] * i1, o[j][3] * i1);
    }
}

extern "C" void kernel_launch(void* const* d_in, const int* in_sizes, int n_in,
                              void* d_out, int out_size) {
    const float* x     = (const float*)d_in[0];
    const float* w_qkv = (const float*)d_in[1];
    const float* w_o   = (const float*)d_in[2];
    float* out         = (float*)d_out;

    float *qkv, *ao;
    cudaGetSymbolAddress((void**)&qkv, g_qkv);
    cudaGetSymbolAddress((void**)&ao,  g_ao);

    cudaFuncSetAttribute(attn_tf32, cudaFuncAttributeMaxDynamicSharedMemorySize, SMEM_ATTN);

    // 1) QKV projection: [4096,1024] x [3072,1024]^T -> [4096,3072]
    gemm_tf32<<<dim3(QKV_W / 128, M_TOT / 128), 256>>>(x, w_qkv, qkv, M_TOT, QKV_W, D_MODEL);

    // 2) causal attention -> [4096,1024]
    attn_tf32<<<dim3(SEQ / 64, NHEAD, BATCH), 128, SMEM_ATTN>>>(qkv, ao);

    // 3) output projection: [4096,1024] x [1024,1024]^T -> d_out
    gemm_tf32<<<dim3(D_MODEL / 128, M_TOT / 128), 256>>>(ao, w_o, out, M_TOT, D_MODEL, D_MODEL);
}

// round 3
// speedup vs baseline: 9.8214x; 1.1140x over previous
#include <cuda_runtime.h>

#define D_MODEL 1024
#define NHEAD   16
#define HD      64
#define SEQ     2048
#define BATCH   2
#define M_TOT   (BATCH * SEQ)   // 4096
#define QKV_W   (3 * D_MODEL)   // 3072

// Scratch (no cudaMalloc allowed).
__device__ float g_qkv[(size_t)M_TOT * QKV_W];   // [4096, 3072]
__device__ float g_ao [(size_t)M_TOT * D_MODEL]; // [4096, 1024]

__device__ __forceinline__ unsigned f2tf(float f) {
    unsigned u;
    asm("cvt.rna.tf32.f32 %0, %1;" : "=r"(u) : "f"(f));
    return u;
}

__device__ __forceinline__ void mma_tf32(float* c, const unsigned* a,
                                         unsigned b0, unsigned b1) {
    asm volatile(
        "mma.sync.aligned.m16n8k8.row.col.f32.tf32.tf32.f32 "
        "{%0,%1,%2,%3},{%4,%5,%6,%7},{%8,%9},{%0,%1,%2,%3};\n"
        : "+f"(c[0]), "+f"(c[1]), "+f"(c[2]), "+f"(c[3])
        : "r"(a[0]), "r"(a[1]), "r"(a[2]), "r"(a[3]), "r"(b0), "r"(b1));
}

__device__ __forceinline__ void cp_async16(void* smem_dst, const void* gmem_src) {
    unsigned s = (unsigned)__cvta_generic_to_shared(smem_dst);
    asm volatile("cp.async.ca.shared.global [%0], [%1], 16;\n" :: "r"(s), "l"(gmem_src));
}
#define CP_COMMIT() asm volatile("cp.async.commit_group;\n" ::: "memory")
#define CP_WAIT1()  asm volatile("cp.async.wait_group 1;\n" ::: "memory")

// ---------------------------------------------------------------------------
// C[m][n] = sum_k A[m][k] * B[n][k]   (A:[M,K], B:[N,K], both row-major)
// 128x128 block tile, K-tile 32, 256 threads (8 warps), tf32 mma.
// Double-buffered smem via cp.async, 2 CTAs/SM.
// smem stride 36 floats: bank = (4*row + col) % 32 -> conflict-free frags.
// ---------------------------------------------------------------------------
#define GSTR 36
#define GTILE (128 * GSTR)
#define SMEM_GEMM (4 * GTILE * 4)   // 2 bufs x (A + B) floats = 73728 B

__global__ __launch_bounds__(256, 2)
void gemm_tf32(const float* __restrict__ A, const float* __restrict__ B,
               float* __restrict__ C, int M, int N, int K) {
    extern __shared__ float smg[];
    // layout: As[buf] = smg + buf*GTILE, Bs[buf] = smg + 2*GTILE + buf*GTILE

    const int t    = threadIdx.x;
    const int lane = t & 31;
    const int w    = t >> 5;
    const int gid  = lane >> 2;
    const int tig  = lane & 3;
    const int wm   = w & 1;
    const int wn   = w >> 1;
    const int m0   = blockIdx.y * 128;
    const int n0   = blockIdx.x * 128;

    const int lr = t >> 3;        // 0..31
    const int lc = (t & 7) * 4;   // 0,4,...,28

    float acc[4][4][4];
#pragma unroll
    for (int i = 0; i < 4; i++)
#pragma unroll
        for (int j = 0; j < 4; j++)
#pragma unroll
            for (int e = 0; e < 4; e++) acc[i][j][e] = 0.f;

    const float* Ap = A + (size_t)(m0 + lr) * K + lc;
    const float* Bp = B + (size_t)(n0 + lr) * K + lc;

    const int nkt = K / 32;

    // prologue: async-load tile 0 into buffer 0
    {
        float* as = smg + lr * GSTR + lc;
        float* bs = smg + 2 * GTILE + lr * GSTR + lc;
#pragma unroll
        for (int p = 0; p < 4; p++) {
            cp_async16(as + p * 32 * GSTR, Ap + (size_t)(p * 32) * K);
            cp_async16(bs + p * 32 * GSTR, Bp + (size_t)(p * 32) * K);
        }
    }
    CP_COMMIT();

    for (int kt = 0; kt < nkt; kt++) {
        const int cur = kt & 1;
        if (kt + 1 < nkt) {
            const int nb = cur ^ 1;
            float* as = smg + nb * GTILE + lr * GSTR + lc;
            float* bs = smg + 2 * GTILE + nb * GTILE + lr * GSTR + lc;
            const float* Ap2 = Ap + (kt + 1) * 32;
            const float* Bp2 = Bp + (kt + 1) * 32;
#pragma unroll
            for (int p = 0; p < 4; p++) {
                cp_async16(as + p * 32 * GSTR, Ap2 + (size_t)(p * 32) * K);
                cp_async16(bs + p * 32 * GSTR, Bp2 + (size_t)(p * 32) * K);
            }
        }
        CP_COMMIT();
        CP_WAIT1();
        __syncthreads();

        const float* As = smg + cur * GTILE;
        const float* Bs = smg + 2 * GTILE + cur * GTILE;
        const int am = wm * 64;
        const int bn = wn * 32;
#pragma unroll
        for (int s = 0; s < 4; s++) {
            const int kk = s * 8;
            unsigned av[4][4];
#pragma unroll
            for (int mi = 0; mi < 4; mi++) {
                const int r = (am + 16 * mi + gid) * GSTR;
                const int r8 = r + 8 * GSTR;
                av[mi][0] = f2tf(As[r + kk + tig]);
                av[mi][1] = f2tf(As[r8 + kk + tig]);
                av[mi][2] = f2tf(As[r + kk + tig + 4]);
                av[mi][3] = f2tf(As[r8 + kk + tig + 4]);
            }
            unsigned bv[4][2];
#pragma unroll
            for (int nj = 0; nj < 4; nj++) {
                const int r = (bn + 8 * nj + gid) * GSTR;
                bv[nj][0] = f2tf(Bs[r + kk + tig]);
                bv[nj][1] = f2tf(Bs[r + kk + tig + 4]);
            }
#pragma unroll
            for (int mi = 0; mi < 4; mi++)
#pragma unroll
                for (int nj = 0; nj < 4; nj++)
                    mma_tf32(acc[mi][nj], av[mi], bv[nj][0], bv[nj][1]);
        }
        __syncthreads();
    }

    // epilogue
#pragma unroll
    for (int mi = 0; mi < 4; mi++) {
        const int r = m0 + wm * 64 + 16 * mi + gid;
#pragma unroll
        for (int nj = 0; nj < 4; nj++) {
            const int c = n0 + wn * 32 + 8 * nj + 2 * tig;
            *(float2*)(C + (size_t)r * N + c)       = make_float2(acc[mi][nj][0], acc[mi][nj][1]);
            *(float2*)(C + (size_t)(r + 8) * N + c) = make_float2(acc[mi][nj][2], acc[mi][nj][3]);
        }
    }
}

// ---------------------------------------------------------------------------
// Causal flash attention, tf32 mma, cp.async double-buffered K/V.
// Grid (32 q-tiles, 16 heads, 2 batch), 128 threads (4 warps).
// q-tiles launched heaviest-first (reverse order) to shrink tail.
// ---------------------------------------------------------------------------
#define KS_STRIDE 68
#define VS_STRIDE 72
#define PS_STRIDE 68
#define KS_ELEMS (64 * KS_STRIDE)
#define VS_ELEMS (64 * VS_STRIDE)
#define SMEM_ATTN ((2 * KS_ELEMS + 2 * VS_ELEMS + 64 * PS_STRIDE) * 4)

__global__ __launch_bounds__(128)
void attn_tf32(const float* __restrict__ qkv, float* __restrict__ out) {
    extern __shared__ float sma[];
    float* KsF = sma;                       // [2][64][KS_STRIDE]
    float* VsF = sma + 2 * KS_ELEMS;        // [2][64][VS_STRIDE]
    unsigned* Ps = (unsigned*)(sma + 2 * KS_ELEMS + 2 * VS_ELEMS);

    const int qt   = gridDim.x - 1 - blockIdx.x;   // heavy tiles first
    const int h    = blockIdx.y;
    const int b    = blockIdx.z;
    const int t    = threadIdx.x;
    const int lane = t & 31;
    const int w    = t >> 5;
    const int gid  = lane >> 2;
    const int tig  = lane & 3;
    const int q0   = qt * 64;

    const int lrow = t >> 4;        // 0..7 (row group for coop loads)
    const int lc4  = (t & 15) * 4;  // 0..60 (float4 col)

    const float* kbase = qkv + (size_t)b * SEQ * QKV_W + D_MODEL + h * HD;
    const float* vbase = kbase + D_MODEL;

    // prologue: async-load K/V tile 0 into buffer 0
    {
        const float* kp = kbase + (size_t)0 * QKV_W;
#pragma unroll
        for (int p = 0; p < 8; p++) {
            const int row = p * 8 + lrow;
            cp_async16(&KsF[row * KS_STRIDE + lc4], kp + (size_t)row * QKV_W + lc4);
            cp_async16(&VsF[row * VS_STRIDE + lc4], vbase + (size_t)row * QKV_W + lc4);
        }
    }
    CP_COMMIT();

    // cooperative Q load -> Ps (scaled by 1/8, tf32)
    {
        const float* qp = qkv + (size_t)(b * SEQ + q0) * QKV_W + h * HD;
#pragma unroll
        for (int p = 0; p < 8; p++) {
            const int row = p * 8 + lrow;
            float4 v = *(const float4*)(qp + (size_t)row * QKV_W + lc4);
            *(uint4*)&Ps[row * PS_STRIDE + lc4] =
                make_uint4(f2tf(v.x * 0.125f), f2tf(v.y * 0.125f),
                           f2tf(v.z * 0.125f), f2tf(v.w * 0.125f));
        }
    }
    __syncthreads();

    // Q fragments -> registers
    unsigned qf[8][4];
    {
        const int r0 = (16 * w + gid) * PS_STRIDE;
        const int r1 = (16 * w + gid + 8) * PS_STRIDE;
#pragma unroll
        for (int s = 0; s < 8; s++) {
            qf[s][0] = Ps[r0 + 8 * s + tig];
            qf[s][1] = Ps[r1 + 8 * s + tig];
            qf[s][2] = Ps[r0 + 8 * s + tig + 4];
            qf[s][3] = Ps[r1 + 8 * s + tig + 4];
        }
    }

    float o[8][4];
#pragma unroll
    for (int j = 0; j < 8; j++)
#pragma unroll
        for (int e = 0; e < 4; e++) o[j][e] = 0.f;
    float m0 = -1e30f, m1 = -1e30f, l0 = 0.f, l1 = 0.f;

    const int row0 = q0 + 16 * w + gid;

    for (int jt = 0; jt <= qt; jt++) {
        const int cur = jt & 1;
        // issue next tile's loads into the other buffer
        if (jt + 1 <= qt) {
            const int nb = cur ^ 1;
            const float* kp = kbase + (size_t)(jt + 1) * 64 * QKV_W;
            const float* vp = vbase + (size_t)(jt + 1) * 64 * QKV_W;
#pragma unroll
            for (int p = 0; p < 8; p++) {
                const int row = p * 8 + lrow;
                cp_async16(&KsF[nb * KS_ELEMS + row * KS_STRIDE + lc4],
                           kp + (size_t)row * QKV_W + lc4);
                cp_async16(&VsF[nb * VS_ELEMS + row * VS_STRIDE + lc4],
                           vp + (size_t)row * QKV_W + lc4);
            }
        }
        CP_COMMIT();
        CP_WAIT1();
        __syncthreads();

        const float* Ks = KsF + cur * KS_ELEMS;
        const float* Vs = VsF + cur * VS_ELEMS;
        const int k0 = jt * 64;

        // S = Q K^T
        float sacc[8][4];
#pragma unroll
        for (int j = 0; j < 8; j++)
#pragma unroll
            for (int e = 0; e < 4; e++) sacc[j][e] = 0.f;

#pragma unroll
        for (int s = 0; s < 8; s++) {
#pragma unroll
            for (int j = 0; j < 8; j++) {
                const int kr = (8 * j + gid) * KS_STRIDE + 8 * s + tig;
                mma_tf32(sacc[j], qf[s], f2tf(Ks[kr]), f2tf(Ks[kr + 4]));
            }
        }

        // mask (diagonal tile) + row max
        float mt0 = -1e30f, mt1 = -1e30f;
#pragma unroll
        for (int j = 0; j < 8; j++) {
            const int cb = k0 + 8 * j + 2 * tig;
            if (jt == qt) {
                if (cb     > row0)     sacc[j][0] = -1e30f;
                if (cb + 1 > row0)     sacc[j][1] = -1e30f;
                if (cb     > row0 + 8) sacc[j][2] = -1e30f;
                if (cb + 1 > row0 + 8) sacc[j][3] = -1e30f;
            }
            mt0 = fmaxf(mt0, fmaxf(sacc[j][0], sacc[j][1]));
            mt1 = fmaxf(mt1, fmaxf(sacc[j][2], sacc[j][3]));
        }
        mt0 = fmaxf(mt0, __shfl_xor_sync(0xffffffffu, mt0, 1));
        mt0 = fmaxf(mt0, __shfl_xor_sync(0xffffffffu, mt0, 2));
        mt1 = fmaxf(mt1, __shfl_xor_sync(0xffffffffu, mt1, 1));
        mt1 = fmaxf(mt1, __shfl_xor_sync(0xffffffffu, mt1, 2));

        const float mn0 = fmaxf(m0, mt0);
        const float mn1 = fmaxf(m1, mt1);
        const float al0 = __expf(m0 - mn0);
        const float al1 = __expf(m1 - mn1);
        m0 = mn0; m1 = mn1;

        // P = exp(S - m) -> warp-private Ps rows (tf32), row sums
        float ls0 = 0.f, ls1 = 0.f;
        {
            const int pr0 = (16 * w + gid) * PS_STRIDE;
            const int pr1 = (16 * w + gid + 8) * PS_STRIDE;
#pragma unroll
            for (int j = 0; j < 8; j++) {
                const int c = 8 * j + 2 * tig;
                float p00 = __expf(sacc[j][0] - mn0);
                float p01 = __expf(sacc[j][1] - mn0);
                float p10 = __expf(sacc[j][2] - mn1);
                float p11 = __expf(sacc[j][3] - mn1);
                ls0 += p00 + p01;
                ls1 += p10 + p11;
                Ps[pr0 + c]     = f2tf(p00);
                Ps[pr0 + c + 1] = f2tf(p01);
                Ps[pr1 + c]     = f2tf(p10);
                Ps[pr1 + c + 1] = f2tf(p11);
            }
        }
        ls0 += __shfl_xor_sync(0xffffffffu, ls0, 1);
        ls0 += __shfl_xor_sync(0xffffffffu, ls0, 2);
        ls1 += __shfl_xor_sync(0xffffffffu, ls1, 1);
        ls1 += __shfl_xor_sync(0xffffffffu, ls1, 2);
        l0 = l0 * al0 + ls0;
        l1 = l1 * al1 + ls1;

#pragma unroll
        for (int j = 0; j < 8; j++) {
            o[j][0] *= al0; o[j][1] *= al0;
            o[j][2] *= al1; o[j][3] *= al1;
        }
        __syncwarp();

        // O += P V
#pragma unroll
        for (int s = 0; s < 8; s++) {
            unsigned pa[4];
            const int pr0 = (16 * w + gid) * PS_STRIDE + 8 * s;
            const int pr1 = (16 * w + gid + 8) * PS_STRIDE + 8 * s;
            pa[0] = Ps[pr0 + tig];
            pa[1] = Ps[pr1 + tig];
            pa[2] = Ps[pr0 + tig + 4];
            pa[3] = Ps[pr1 + tig + 4];
#pragma unroll
            for (int j = 0; j < 8; j++) {
                const int vb = (8 * s + tig) * VS_STRIDE + 8 * j + gid;
                mma_tf32(o[j], pa, f2tf(Vs[vb]), f2tf(Vs[vb + 4 * VS_STRIDE]));
            }
        }
        __syncthreads();   // done reading cur before it is overwritten
    }

    const float i0 = 1.f / l0;
    const float i1 = 1.f / l1;
    float* op0 = out + (size_t)(b * SEQ + row0) * D_MODEL + h * HD;
    float* op1 = op0 + (size_t)8 * D_MODEL;
#pragma unroll
    for (int j = 0; j < 8; j++) {
        const int c = 8 * j + 2 * tig;
        *(float2*)(op0 + c) = make_float2(o[j][0] * i0, o[j][1] * i0);
        *(float2*)(op1 + c) = make_float2(o[j][2] * i1, o[j][3] * i1);
    }
}

extern "C" void kernel_launch(void* const* d_in, const int* in_sizes, int n_in,
                              void* d_out, int out_size) {
    const float* x     = (const float*)d_in[0];
    const float* w_qkv = (const float*)d_in[1];
    const float* w_o   = (const float*)d_in[2];
    float* out         = (float*)d_out;

    float *qkv, *ao;
    cudaGetSymbolAddress((void**)&qkv, g_qkv);
    cudaGetSymbolAddress((void**)&ao,  g_ao);

    static bool attr_set = false;
    if (!attr_set) {
        cudaFuncSetAttribute(gemm_tf32, cudaFuncAttributeMaxDynamicSharedMemorySize, SMEM_GEMM);
        cudaFuncSetAttribute(attn_tf32, cudaFuncAttributeMaxDynamicSharedMemorySize, SMEM_ATTN);
        attr_set = true;
    }

    gemm_tf32<<<dim3(QKV_W / 128, M_TOT / 128), 256, SMEM_GEMM>>>(x, w_qkv, qkv, M_TOT, QKV_W, D_MODEL);
    attn_tf32<<<dim3(SEQ / 64, NHEAD, BATCH), 128, SMEM_ATTN>>>(qkv, ao);
    gemm_tf32<<<dim3(D_MODEL / 128, M_TOT / 128), 256, SMEM_GEMM>>>(ao, w_o, out, M_TOT, D_MODEL, D_MODEL);
}

// round 4
// speedup vs baseline: 10.7925x; 1.0989x over previous
#include <cuda_runtime.h>

#define D_MODEL 1024
#define NHEAD   16
#define HD      64
#define SEQ     2048
#define BATCH   2
#define M_TOT   (BATCH * SEQ)   // 4096
#define QKV_W   (3 * D_MODEL)   // 3072

// Scratch (no cudaMalloc allowed). All hold tf32 bit patterns.
__device__ unsigned g_qkv[(size_t)M_TOT * QKV_W];   // [4096,3072] tf32
__device__ unsigned g_ao [(size_t)M_TOT * D_MODEL]; // [4096,1024] tf32
__device__ unsigned g_xc [(size_t)M_TOT * D_MODEL]; // x  -> tf32
__device__ unsigned g_wq [(size_t)QKV_W * D_MODEL]; // w_qkv -> tf32
__device__ unsigned g_wo [(size_t)D_MODEL * D_MODEL]; // w_o -> tf32

__device__ __forceinline__ unsigned f2tf(float f) {
    unsigned u;
    asm("cvt.rna.tf32.f32 %0, %1;" : "=r"(u) : "f"(f));
    return u;
}

__device__ __forceinline__ void mma_tf32(float* c, const unsigned* a,
                                         unsigned b0, unsigned b1) {
    asm volatile(
        "mma.sync.aligned.m16n8k8.row.col.f32.tf32.tf32.f32 "
        "{%0,%1,%2,%3},{%4,%5,%6,%7},{%8,%9},{%0,%1,%2,%3};\n"
        : "+f"(c[0]), "+f"(c[1]), "+f"(c[2]), "+f"(c[3])
        : "r"(a[0]), "r"(a[1]), "r"(a[2]), "r"(a[3]), "r"(b0), "r"(b1));
}

__device__ __forceinline__ void cp_async16(void* smem_dst, const void* gmem_src) {
    unsigned s = (unsigned)__cvta_generic_to_shared(smem_dst);
    asm volatile("cp.async.ca.shared.global [%0], [%1], 16;\n" :: "r"(s), "l"(gmem_src));
}
#define CP_COMMIT() asm volatile("cp.async.commit_group;\n" ::: "memory")
#define CP_WAIT1()  asm volatile("cp.async.wait_group 1;\n" ::: "memory")
#define CP_WAIT0()  asm volatile("cp.async.wait_group 0;\n" ::: "memory")

// ---------------------------------------------------------------------------
// Pre-convert fp32 inputs -> tf32 bits (one fused elementwise pass, float4).
// ---------------------------------------------------------------------------
#define XC_F4 ((M_TOT * D_MODEL) / 4)
#define WQ_F4 ((QKV_W * D_MODEL) / 4)
#define WO_F4 ((D_MODEL * D_MODEL) / 4)
#define CONV_BLOCKS ((XC_F4 + WQ_F4 + WO_F4) / 256)

__global__ void conv_tf32(const float4* __restrict__ x,
                          const float4* __restrict__ wq,
                          const float4* __restrict__ wo,
                          uint4* __restrict__ ox,
                          uint4* __restrict__ owq,
                          uint4* __restrict__ owo) {
    const int idx = blockIdx.x * 256 + threadIdx.x;
    const float4* src;
    uint4* dst;
    int i;
    if (idx < XC_F4)                { src = x;  dst = ox;  i = idx; }
    else if (idx < XC_F4 + WQ_F4)   { src = wq; dst = owq; i = idx - XC_F4; }
    else                            { src = wo; dst = owo; i = idx - XC_F4 - WQ_F4; }
    float4 v = src[i];
    dst[i] = make_uint4(f2tf(v.x), f2tf(v.y), f2tf(v.z), f2tf(v.w));
}

// ---------------------------------------------------------------------------
// C[m][n] = sum_k A[m][k]*B[n][k], A/B tf32 bits. 128x128 tile, K-tile 32,
// 256 threads, cp.async double-buffered, zero cvt in mainloop.
// OUT_TF32: write C as tf32 bits (for chained consumers) or fp32.
// ---------------------------------------------------------------------------
#define GSTR 36
#define GTILE (128 * GSTR)
#define SMEM_GEMM (4 * GTILE * 4)

template <bool OUT_TF32>
__global__ __launch_bounds__(256, 2)
void gemm_tt(const unsigned* __restrict__ A, const unsigned* __restrict__ B,
             void* __restrict__ Cv, int M, int N, int K) {
    extern __shared__ unsigned smg[];

    const int t    = threadIdx.x;
    const int lane = t & 31;
    const int w    = t >> 5;
    const int gid  = lane >> 2;
    const int tig  = lane & 3;
    const int wm   = w & 1;
    const int wn   = w >> 1;
    const int m0   = blockIdx.y * 128;
    const int n0   = blockIdx.x * 128;

    const int lr = t >> 3;
    const int lc = (t & 7) * 4;

    float acc[4][4][4];
#pragma unroll
    for (int i = 0; i < 4; i++)
#pragma unroll
        for (int j = 0; j < 4; j++)
#pragma unroll
            for (int e = 0; e < 4; e++) acc[i][j][e] = 0.f;

    const unsigned* Ap = A + (size_t)(m0 + lr) * K + lc;
    const unsigned* Bp = B + (size_t)(n0 + lr) * K + lc;

    const int nkt = K / 32;

    {
        unsigned* as = smg + lr * GSTR + lc;
        unsigned* bs = smg + 2 * GTILE + lr * GSTR + lc;
#pragma unroll
        for (int p = 0; p < 4; p++) {
            cp_async16(as + p * 32 * GSTR, Ap + (size_t)(p * 32) * K);
            cp_async16(bs + p * 32 * GSTR, Bp + (size_t)(p * 32) * K);
        }
    }
    CP_COMMIT();

    for (int kt = 0; kt < nkt; kt++) {
        const int cur = kt & 1;
        if (kt + 1 < nkt) {
            const int nb = cur ^ 1;
            unsigned* as = smg + nb * GTILE + lr * GSTR + lc;
            unsigned* bs = smg + 2 * GTILE + nb * GTILE + lr * GSTR + lc;
            const unsigned* Ap2 = Ap + (kt + 1) * 32;
            const unsigned* Bp2 = Bp + (kt + 1) * 32;
#pragma unroll
            for (int p = 0; p < 4; p++) {
                cp_async16(as + p * 32 * GSTR, Ap2 + (size_t)(p * 32) * K);
                cp_async16(bs + p * 32 * GSTR, Bp2 + (size_t)(p * 32) * K);
            }
        }
        CP_COMMIT();
        CP_WAIT1();
        __syncthreads();

        const unsigned* As = smg + cur * GTILE;
        const unsigned* Bs = smg + 2 * GTILE + cur * GTILE;
        const int am = wm * 64;
        const int bn = wn * 32;
#pragma unroll
        for (int s = 0; s < 4; s++) {
            const int kk = s * 8;
            unsigned av[4][4];
#pragma unroll
            for (int mi = 0; mi < 4; mi++) {
                const int r  = (am + 16 * mi + gid) * GSTR;
                const int r8 = r + 8 * GSTR;
                av[mi][0] = As[r + kk + tig];
                av[mi][1] = As[r8 + kk + tig];
                av[mi][2] = As[r + kk + tig + 4];
                av[mi][3] = As[r8 + kk + tig + 4];
            }
            unsigned bv[4][2];
#pragma unroll
            for (int nj = 0; nj < 4; nj++) {
                const int r = (bn + 8 * nj + gid) * GSTR;
                bv[nj][0] = Bs[r + kk + tig];
                bv[nj][1] = Bs[r + kk + tig + 4];
            }
#pragma unroll
            for (int mi = 0; mi < 4; mi++)
#pragma unroll
                for (int nj = 0; nj < 4; nj++)
                    mma_tf32(acc[mi][nj], av[mi], bv[nj][0], bv[nj][1]);
        }
        __syncthreads();
    }

    // epilogue
#pragma unroll
    for (int mi = 0; mi < 4; mi++) {
        const int r = m0 + wm * 64 + 16 * mi + gid;
#pragma unroll
        for (int nj = 0; nj < 4; nj++) {
            const int c = n0 + wn * 32 + 8 * nj + 2 * tig;
            if (OUT_TF32) {
                unsigned* C = (unsigned*)Cv;
                *(uint2*)(C + (size_t)r * N + c) =
                    make_uint2(f2tf(acc[mi][nj][0]), f2tf(acc[mi][nj][1]));
                *(uint2*)(C + (size_t)(r + 8) * N + c) =
                    make_uint2(f2tf(acc[mi][nj][2]), f2tf(acc[mi][nj][3]));
            } else {
                float* C = (float*)Cv;
                *(float2*)(C + (size_t)r * N + c) =
                    make_float2(acc[mi][nj][0], acc[mi][nj][1]);
                *(float2*)(C + (size_t)(r + 8) * N + c) =
                    make_float2(acc[mi][nj][2], acc[mi][nj][3]);
            }
        }
    }
}

// ---------------------------------------------------------------------------
// Causal flash attention, tf32 in / tf32 out, cp.async double-buffered K/V,
// zero cvt in S and PV loops (only P gets rna cvt).
// ---------------------------------------------------------------------------
#define KS_STRIDE 68
#define VS_STRIDE 72
#define PS_STRIDE 68
#define KS_ELEMS (64 * KS_STRIDE)
#define VS_ELEMS (64 * VS_STRIDE)
#define SMEM_ATTN ((2 * KS_ELEMS + 2 * VS_ELEMS + 64 * PS_STRIDE) * 4)

__global__ __launch_bounds__(128)
void attn_tf32(const unsigned* __restrict__ qkv, unsigned* __restrict__ out) {
    extern __shared__ unsigned sma[];
    unsigned* KsF = sma;
    unsigned* VsF = sma + 2 * KS_ELEMS;
    unsigned* Ps  = sma + 2 * KS_ELEMS + 2 * VS_ELEMS;

    const int qt   = gridDim.x - 1 - blockIdx.x;   // heavy tiles first
    const int h    = blockIdx.y;
    const int b    = blockIdx.z;
    const int t    = threadIdx.x;
    const int lane = t & 31;
    const int w    = t >> 5;
    const int gid  = lane >> 2;
    const int tig  = lane & 3;
    const int q0   = qt * 64;

    const int lrow = t >> 4;
    const int lc4  = (t & 15) * 4;

    const unsigned* kbase = qkv + (size_t)b * SEQ * QKV_W + D_MODEL + h * HD;
    const unsigned* vbase = kbase + D_MODEL;

    // prologue group 0: Q tile + K/V tile 0
    {
        const unsigned* qp = qkv + (size_t)(b * SEQ + q0) * QKV_W + h * HD;
#pragma unroll
        for (int p = 0; p < 8; p++) {
            const int row = p * 8 + lrow;
            cp_async16(&Ps[row * PS_STRIDE + lc4], qp + (size_t)row * QKV_W + lc4);
            cp_async16(&KsF[row * KS_STRIDE + lc4], kbase + (size_t)row * QKV_W + lc4);
            cp_async16(&VsF[row * VS_STRIDE + lc4], vbase + (size_t)row * QKV_W + lc4);
        }
    }
    CP_COMMIT();
    CP_WAIT0();
    __syncthreads();

    // Q fragments -> registers (scale by exact power of two: no rounding)
    unsigned qf[8][4];
    {
        const int r0 = (16 * w + gid) * PS_STRIDE;
        const int r1 = (16 * w + gid + 8) * PS_STRIDE;
#pragma unroll
        for (int s = 0; s < 8; s++) {
            qf[s][0] = __float_as_uint(__uint_as_float(Ps[r0 + 8 * s + tig]) * 0.125f);
            qf[s][1] = __float_as_uint(__uint_as_float(Ps[r1 + 8 * s + tig]) * 0.125f);
            qf[s][2] = __float_as_uint(__uint_as_float(Ps[r0 + 8 * s + tig + 4]) * 0.125f);
            qf[s][3] = __float_as_uint(__uint_as_float(Ps[r1 + 8 * s + tig + 4]) * 0.125f);
        }
    }

    float o[8][4];
#pragma unroll
    for (int j = 0; j < 8; j++)
#pragma unroll
        for (int e = 0; e < 4; e++) o[j][e] = 0.f;
    float m0 = -1e30f, m1 = -1e30f, l0 = 0.f, l1 = 0.f;

    const int row0 = q0 + 16 * w + gid;

    for (int jt = 0; jt <= qt; jt++) {
        const int cur = jt & 1;
        if (jt + 1 <= qt) {
            const int nb = cur ^ 1;
            const unsigned* kp = kbase + (size_t)(jt + 1) * 64 * QKV_W;
            const unsigned* vp = vbase + (size_t)(jt + 1) * 64 * QKV_W;
#pragma unroll
            for (int p = 0; p < 8; p++) {
                const int row = p * 8 + lrow;
                cp_async16(&KsF[nb * KS_ELEMS + row * KS_STRIDE + lc4],
                           kp + (size_t)row * QKV_W + lc4);
                cp_async16(&VsF[nb * VS_ELEMS + row * VS_STRIDE + lc4],
                           vp + (size_t)row * QKV_W + lc4);
            }
        }
        CP_COMMIT();
        CP_WAIT1();
        __syncthreads();

        const unsigned* Ks = KsF + cur * KS_ELEMS;
        const unsigned* Vs = VsF + cur * VS_ELEMS;
        const int k0 = jt * 64;

        // S = Q K^T
        float sacc[8][4];
#pragma unroll
        for (int j = 0; j < 8; j++)
#pragma unroll
            for (int e = 0; e < 4; e++) sacc[j][e] = 0.f;

#pragma unroll
        for (int s = 0; s < 8; s++) {
#pragma unroll
            for (int j = 0; j < 8; j++) {
                const int kr = (8 * j + gid) * KS_STRIDE + 8 * s + tig;
                mma_tf32(sacc[j], qf[s], Ks[kr], Ks[kr + 4]);
            }
        }

        // mask + row max
        float mt0 = -1e30f, mt1 = -1e30f;
#pragma unroll
        for (int j = 0; j < 8; j++) {
            const int cb = k0 + 8 * j + 2 * tig;
            if (jt == qt) {
                if (cb     > row0)     sacc[j][0] = -1e30f;
                if (cb + 1 > row0)     sacc[j][1] = -1e30f;
                if (cb     > row0 + 8) sacc[j][2] = -1e30f;
                if (cb + 1 > row0 + 8) sacc[j][3] = -1e30f;
            }
            mt0 = fmaxf(mt0, fmaxf(sacc[j][0], sacc[j][1]));
            mt1 = fmaxf(mt1, fmaxf(sacc[j][2], sacc[j][3]));
        }
        mt0 = fmaxf(mt0, __shfl_xor_sync(0xffffffffu, mt0, 1));
        mt0 = fmaxf(mt0, __shfl_xor_sync(0xffffffffu, mt0, 2));
        mt1 = fmaxf(mt1, __shfl_xor_sync(0xffffffffu, mt1, 1));
        mt1 = fmaxf(mt1, __shfl_xor_sync(0xffffffffu, mt1, 2));

        const float mn0 = fmaxf(m0, mt0);
        const float mn1 = fmaxf(m1, mt1);
        const float al0 = __expf(m0 - mn0);
        const float al1 = __expf(m1 - mn1);
        m0 = mn0; m1 = mn1;

        // P = exp(S - m) -> Ps rows (tf32), row sums
        float ls0 = 0.f, ls1 = 0.f;
        {
            const int pr0 = (16 * w + gid) * PS_STRIDE;
            const int pr1 = (16 * w + gid + 8) * PS_STRIDE;
#pragma unroll
            for (int j = 0; j < 8; j++) {
                const int c = 8 * j + 2 * tig;
                float p00 = __expf(sacc[j][0] - mn0);
                float p01 = __expf(sacc[j][1] - mn0);
                float p10 = __expf(sacc[j][2] - mn1);
                float p11 = __expf(sacc[j][3] - mn1);
                ls0 += p00 + p01;
                ls1 += p10 + p11;
                Ps[pr0 + c]     = f2tf(p00);
                Ps[pr0 + c + 1] = f2tf(p01);
                Ps[pr1 + c]     = f2tf(p10);
                Ps[pr1 + c + 1] = f2tf(p11);
            }
        }
        ls0 += __shfl_xor_sync(0xffffffffu, ls0, 1);
        ls0 += __shfl_xor_sync(0xffffffffu, ls0, 2);
        ls1 += __shfl_xor_sync(0xffffffffu, ls1, 1);
        ls1 += __shfl_xor_sync(0xffffffffu, ls1, 2);
        l0 = l0 * al0 + ls0;
        l1 = l1 * al1 + ls1;

#pragma unroll
        for (int j = 0; j < 8; j++) {
            o[j][0] *= al0; o[j][1] *= al0;
            o[j][2] *= al1; o[j][3] *= al1;
        }
        __syncwarp();

        // O += P V
#pragma unroll
        for (int s = 0; s < 8; s++) {
            unsigned pa[4];
            const int pr0 = (16 * w + gid) * PS_STRIDE + 8 * s;
            const int pr1 = (16 * w + gid + 8) * PS_STRIDE + 8 * s;
            pa[0] = Ps[pr0 + tig];
            pa[1] = Ps[pr1 + tig];
            pa[2] = Ps[pr0 + tig + 4];
            pa[3] = Ps[pr1 + tig + 4];
#pragma unroll
            for (int j = 0; j < 8; j++) {
                const int vb = (8 * s + tig) * VS_STRIDE + 8 * j + gid;
                mma_tf32(o[j], pa, Vs[vb], Vs[vb + 4 * VS_STRIDE]);
            }
        }
        __syncthreads();
    }

    // epilogue -> tf32 bits for the output projection
    const float i0 = 1.f / l0;
    const float i1 = 1.f / l1;
    unsigned* op0 = out + (size_t)(b * SEQ + row0) * D_MODEL + h * HD;
    unsigned* op1 = op0 + (size_t)8 * D_MODEL;
#pragma unroll
    for (int j = 0; j < 8; j++) {
        const int c = 8 * j + 2 * tig;
        *(uint2*)(op0 + c) = make_uint2(f2tf(o[j][0] * i0), f2tf(o[j][1] * i0));
        *(uint2*)(op1 + c) = make_uint2(f2tf(o[j][2] * i1), f2tf(o[j][3] * i1));
    }
}

extern "C" void kernel_launch(void* const* d_in, const int* in_sizes, int n_in,
                              void* d_out, int out_size) {
    const float* x     = (const float*)d_in[0];
    const float* w_qkv = (const float*)d_in[1];
    const float* w_o   = (const float*)d_in[2];
    float* out         = (float*)d_out;

    unsigned *qkv, *ao, *xc, *wq, *wo;
    cudaGetSymbolAddress((void**)&qkv, g_qkv);
    cudaGetSymbolAddress((void**)&ao,  g_ao);
    cudaGetSymbolAddress((void**)&xc,  g_xc);
    cudaGetSymbolAddress((void**)&wq,  g_wq);
    cudaGetSymbolAddress((void**)&wo,  g_wo);

    static bool attr_set = false;
    if (!attr_set) {
        cudaFuncSetAttribute(gemm_tt<true>,  cudaFuncAttributeMaxDynamicSharedMemorySize, SMEM_GEMM);
        cudaFuncSetAttribute(gemm_tt<false>, cudaFuncAttributeMaxDynamicSharedMemorySize, SMEM_GEMM);
        cudaFuncSetAttribute(attn_tf32, cudaFuncAttributeMaxDynamicSharedMemorySize, SMEM_ATTN);
        attr_set = true;
    }

    // 0) fp32 -> tf32 pre-pass for x, w_qkv, w_o
    conv_tf32<<<CONV_BLOCKS, 256>>>((const float4*)x, (const float4*)w_qkv, (const float4*)w_o,
                                    (uint4*)xc, (uint4*)wq, (uint4*)wo);

    // 1) QKV projection (writes tf32)
    gemm_tt<true><<<dim3(QKV_W / 128, M_TOT / 128), 256, SMEM_GEMM>>>(xc, wq, qkv, M_TOT, QKV_W, D_MODEL);

    // 2) causal attention (tf32 -> tf32)
    attn_tf32<<<dim3(SEQ / 64, NHEAD, BATCH), 128, SMEM_ATTN>>>(qkv, ao);

    // 3) output projection (writes fp32 to d_out)
    gemm_tt<false><<<dim3(D_MODEL / 128, M_TOT / 128), 256, SMEM_GEMM>>>(ao, wo, out, M_TOT, D_MODEL, D_MODEL);
}